// round 7
// baseline (speedup 1.0000x reference)
#include <cuda_runtime.h>
#include <math.h>

// TsCv: sliding-window coefficient of variation.
// x: (64, 256, 4096) fp32  -> out: (64, 256, 816) fp32
// window = 20, stride = 5, var ddof=1, cv = std/(mean+1e-8), NaN -> 0.
//
// Numerics: the window-SUM bit pattern must match the reference exactly
// (catastrophic cancellation in mean+1e-8). Model: reference ran under
// XLA:GPU; its row-reduction emitter puts one element per warp lane
// (lanes 20..31 = 0.0, exact) and reduces with shfl_down 16,8,4,2,1:
//   A_j = ((w_j + w_{16+j}) + w_{8+j}) + (w_{4+j} + w_{12+j})   j=0..3
//   sum = (A0 + A2) + (A1 + A3)
// Same tree for the squared-deviation sum. No FMA contraction anywhere.

#define SEQ_LEN   4096
#define MIN_W     20
#define STRIDE_W  5
#define OUT_LEN   ((SEQ_LEN - MIN_W) / STRIDE_W + 1)   // 816
#define EPS_CV    1e-8f
#define BLOCK_T   256

__device__ __forceinline__ float warp_tree_sum20(const float* __restrict__ w)
{
    // shfl_down butterfly over 32 lanes, elements 20..31 are +0.0 (exact adds).
    float A0 = __fadd_rn(__fadd_rn(__fadd_rn(w[0], w[16]), w[8]),
                         __fadd_rn(w[4], w[12]));
    float A1 = __fadd_rn(__fadd_rn(__fadd_rn(w[1], w[17]), w[9]),
                         __fadd_rn(w[5], w[13]));
    float A2 = __fadd_rn(__fadd_rn(__fadd_rn(w[2], w[18]), w[10]),
                         __fadd_rn(w[6], w[14]));
    float A3 = __fadd_rn(__fadd_rn(__fadd_rn(w[3], w[19]), w[11]),
                         __fadd_rn(w[7], w[15]));
    return __fadd_rn(__fadd_rn(A0, A2), __fadd_rn(A1, A3));
}

__global__ __launch_bounds__(BLOCK_T)
void TsCv_29257317220818_kernel(const float* __restrict__ x,
                                float* __restrict__ out)
{
    __shared__ float row[SEQ_LEN];

    const int r = blockIdx.x;                 // flattened (b, f) row index
    const float* __restrict__ src = x + (size_t)r * SEQ_LEN;

    // Coalesced vectorized row load: 4096 floats = 1024 float4, 4 per thread.
    const float4* __restrict__ src4 = (const float4*)src;
    float4* row4 = (float4*)row;
    #pragma unroll
    for (int i = 0; i < SEQ_LEN / 4 / BLOCK_T; i++) {
        row4[threadIdx.x + i * BLOCK_T] = src4[threadIdx.x + i * BLOCK_T];
    }
    __syncthreads();

    float* __restrict__ dst = out + (size_t)r * OUT_LEN;

    for (int o = threadIdx.x; o < OUT_LEN; o += BLOCK_T) {
        const int s = o * STRIDE_W;

        // Window in registers.
        float w[MIN_W];
        #pragma unroll
        for (int k = 0; k < MIN_W; k++) w[k] = row[s + k];

        // ---- mean: warp-shuffle tree order ----
        const float sum  = warp_tree_sum20(w);
        const float mean = __fdiv_rn(sum, (float)MIN_W);

        // ---- squared deviations: same tree, no FMA ----
        float d[MIN_W];
        #pragma unroll
        for (int k = 0; k < MIN_W; k++) {
            float dd = __fadd_rn(w[k], -mean);
            d[k] = __fmul_rn(dd, dd);
        }
        const float ssd = warp_tree_sum20(d);

        const float var = __fdiv_rn(ssd, (float)(MIN_W - 1));
        const float sd  = sqrtf(var);

        const float den = __fadd_rn(mean, EPS_CV);
        float cv = __fdiv_rn(sd, den);
        if (isnan(cv)) cv = 0.0f;
        dst[o] = cv;
    }
}

extern "C" void kernel_launch(void* const* d_in, const int* in_sizes, int n_in,
                              void* d_out, int out_size)
{
    const float* x = (const float*)d_in[0];
    float* out = (float*)d_out;

    const int n_rows = in_sizes[0] / SEQ_LEN;   // 64 * 256 = 16384
    TsCv_29257317220818_kernel<<<n_rows, BLOCK_T>>>(x, out);
}